// round 12
// baseline (speedup 1.0000x reference)
#include <cuda_runtime.h>
#include <math.h>
#include <stdint.h>

#define FULLMASK 0xffffffffu

constexpr int N_ = 4, C_ = 64, F_ = 100, T_ = 200, H_ = 16;
constexpr int B_  = N_ * F_;        // 400
constexpr int BT_ = B_ * T_;        // 80000
constexpr int NJ  = 24;             // 8 branches * 3 lstms
constexpr int BC_ = 80;             // batch chunk for k2/k3 L2-residency interleave

// ---------------- scratch (static device globals; no allocation) ----------------
__device__ float g_xln[(size_t)2 * BT_ * C_];        // [2][B][T][C]
__device__ float g_xg [(size_t)NJ * BT_ * C_];       // [24][B*T][64]
__device__ float g_qkv[(size_t)NJ * B_ * T_ * H_];   // [24][B][T][16]
__device__ float g_att[(size_t)8  * B_ * T_ * H_];   // [8][B][T][16]

__constant__ int SRC[24] = {0,0,0, 0,1,1, 1,0,1, 1,1,0, 0,0,1, 0,1,0, 1,0,0, 1,1,1};

__device__ __forceinline__ float sigf(float x)   { return 1.0f / (1.0f + __expf(-x)); }
__device__ __forceinline__ float tanhf_(float x) { return 2.0f / (1.0f + __expf(-2.0f * x)) - 1.0f; }

__device__ __forceinline__ uint32_t f2tf32(float x) {
    uint32_t r;
    asm("cvt.rna.tf32.f32 %0, %1;" : "=r"(r) : "f"(x));
    return r;
}

__device__ __forceinline__ void mma_tf32(float c[4],
                                         uint32_t a0, uint32_t a1, uint32_t a2, uint32_t a3,
                                         uint32_t b0, uint32_t b1) {
    asm volatile(
        "mma.sync.aligned.m16n8k8.row.col.f32.tf32.tf32.f32 "
        "{%0,%1,%2,%3}, {%4,%5,%6,%7}, {%8,%9}, {%0,%1,%2,%3};\n"
        : "+f"(c[0]), "+f"(c[1]), "+f"(c[2]), "+f"(c[3])
        : "r"(a0), "r"(a1), "r"(a2), "r"(a3), "r"(b0), "r"(b1));
}

// ---------------- kernel 1: permute + LayerNorm1 (coalesced via smem transpose) --
__global__ void k1_ln1(const float* __restrict__ inp,
                       const float* __restrict__ w, const float* __restrict__ bb)
{
    __shared__ float xs[2][40][65];
    int bid = blockIdx.x;
    int tile = bid % 5, nf = bid / 5;
    int n = nf / 100, f = nf % 100;
    int t0 = tile * 40;
    int tid = threadIdx.x;

    int c = tid >> 2, q = tid & 3;
    const float* base = inp + ((size_t)(n * 64 + c) * 100 + f) * 400 + (size_t)t0 * 2;
#pragma unroll
    for (int i = 0; i < 10; i++) {
        int tt = q * 10 + i;
        float2 v = *(const float2*)(base + tt * 2);
        xs[0][tt][c] = v.x;
        xs[1][tt][c] = v.y;
    }
    __syncthreads();

    int warp = tid >> 5, lane = tid & 31;
    int c0 = lane, c1 = lane + 32;
    float w0 = w[c0], w1 = w[c1], b0 = bb[c0], b1 = bb[c1];

#pragma unroll
    for (int kk = 0; kk < 5; kk++) {
        int tt = warp + kk * 8;
        float vx0 = xs[0][tt][c0], vx1 = xs[0][tt][c1];
        float vy0 = xs[1][tt][c0], vy1 = xs[1][tt][c1];
        float sx = vx0 + vx1, sxx = vx0 * vx0 + vx1 * vx1;
        float sy = vy0 + vy1, syy = vy0 * vy0 + vy1 * vy1;
#pragma unroll
        for (int off = 16; off; off >>= 1) {
            sx  += __shfl_xor_sync(FULLMASK, sx,  off);
            sxx += __shfl_xor_sync(FULLMASK, sxx, off);
            sy  += __shfl_xor_sync(FULLMASK, sy,  off);
            syy += __shfl_xor_sync(FULLMASK, syy, off);
        }
        float mx = sx * (1.0f / 64.0f), my = sy * (1.0f / 64.0f);
        float rx = rsqrtf(sxx * (1.0f / 64.0f) - mx * mx + 1e-5f);
        float ry = rsqrtf(syy * (1.0f / 64.0f) - my * my + 1e-5f);
        int pos = nf * 200 + t0 + tt;
        float* o0 = g_xln + (size_t)pos * C_;
        float* o1 = g_xln + (size_t)BT_ * C_ + (size_t)pos * C_;
        o0[c0] = (vx0 - mx) * rx * w0 + b0;
        o0[c1] = (vx1 - mx) * rx * w1 + b1;
        o1[c0] = (vy0 - my) * ry * w0 + b0;
        o1[c1] = (vy1 - my) * ry * w1 + b1;
    }
}

// ---------------- kernel 2: xg = xln[src] @ Wih^T via tf32 MMA (2-term comp) ----
// chunked over batch: grid (125, 24) per chunk; 256 thr = 8 warps x 16 rows.
__global__ void __launch_bounds__(256) k2_gemm(const float* __restrict__ Wih,
                        const float* __restrict__ bih, const float* __restrict__ bhh,
                        int b0c)
{
    __shared__ float As[64][136];
    __shared__ float Ws[64][72];
    int j   = blockIdx.y;
    int src = SRC[j];
    size_t rowoff = (size_t)b0c * T_ * 1 + 0;                 // b0c*200 rows
    size_t base   = ((size_t)b0c * T_) * 64;
    int bt0 = blockIdx.x * 128;
    int tid = threadIdx.x;
    (void)rowoff;

    const float* A = g_xln + (size_t)src * BT_ * C_ + base + (size_t)bt0 * C_;
    const float* W = Wih + (size_t)j * 4096;
#pragma unroll
    for (int it = 0; it < 32; ++it) {
        int idx = it * 256 + tid;
        int rr = idx >> 6, kk = idx & 63;
        As[kk][rr] = A[idx];
    }
#pragma unroll
    for (int it = 0; it < 16; ++it) {
        int idx = it * 256 + tid;
        int rr = idx >> 6, kk = idx & 63;
        Ws[kk][rr] = W[idx];
    }
    __syncthreads();

    int warp = tid >> 5, lane = tid & 31;
    int grp = lane >> 2, tid4 = lane & 3;
    int rbase = warp * 16;

    float2 bv[8];
#pragma unroll
    for (int nb = 0; nb < 8; nb++) {
        int col = nb * 8 + tid4 * 2;
        bv[nb].x = bih[j * 64 + col]     + bhh[j * 64 + col];
        bv[nb].y = bih[j * 64 + col + 1] + bhh[j * 64 + col + 1];
    }

    float acc[8][4];
#pragma unroll
    for (int nb = 0; nb < 8; nb++)
#pragma unroll
        for (int x = 0; x < 4; x++) acc[nb][x] = 0.0f;

#pragma unroll
    for (int ks = 0; ks < 8; ks++) {
        int kc = ks * 8 + tid4;
        float a0f = As[kc][rbase + grp];
        float a1f = As[kc][rbase + grp + 8];
        float a2f = As[kc + 4][rbase + grp];
        float a3f = As[kc + 4][rbase + grp + 8];
        uint32_t a0h = f2tf32(a0f), a1h = f2tf32(a1f), a2h = f2tf32(a2f), a3h = f2tf32(a3f);
        uint32_t a0l = __float_as_uint(a0f - __uint_as_float(a0h));
        uint32_t a1l = __float_as_uint(a1f - __uint_as_float(a1h));
        uint32_t a2l = __float_as_uint(a2f - __uint_as_float(a2h));
        uint32_t a3l = __float_as_uint(a3f - __uint_as_float(a3h));
#pragma unroll
        for (int nb = 0; nb < 8; nb++) {
            uint32_t b0h = f2tf32(Ws[kc][nb * 8 + grp]);
            uint32_t b1h = f2tf32(Ws[kc + 4][nb * 8 + grp]);
            mma_tf32(acc[nb], a0h, a1h, a2h, a3h, b0h, b1h);
            mma_tf32(acc[nb], a0l, a1l, a2l, a3l, b0h, b1h);
        }
    }

    float* O = g_xg + (size_t)j * BT_ * 64 + base + (size_t)bt0 * 64;
    int row0 = rbase + grp, row1 = rbase + grp + 8;
#pragma unroll
    for (int nb = 0; nb < 8; nb++) {
        int col = nb * 8 + tid4 * 2;
        *(float2*)&O[row0 * 64 + col] = make_float2(acc[nb][0] + bv[nb].x, acc[nb][1] + bv[nb].y);
        *(float2*)&O[row1 * 64 + col] = make_float2(acc[nb][2] + bv[nb].x, acc[nb][3] + bv[nb].y);
    }
}

// ---------------- kernel 3: LSTM recurrence (chunked over batch) ----------------
// per chunk: 960 warps = 24 j x 40 b-pairs; grid 240 x 128 thr.
__global__ void k3_lstm(const float* __restrict__ Whh, int b0c)
{
    int gw   = blockIdx.x * 4 + (threadIdx.x >> 5);  // 0..959
    int lane = threadIdx.x & 31;
    int j  = gw / 40;
    int bp = gw % 40;
    int seq = lane >> 4, jh = lane & 15;
    int b = b0c + bp * 2 + seq;

    float wr[4][16];
#pragma unroll
    for (int g = 0; g < 4; g++)
#pragma unroll
        for (int k = 0; k < 16; k++)
            wr[g][k] = Whh[j * 1024 + (g * 16 + jh) * 16 + k];

    const float* xgp  = g_xg  + ((size_t)j * B_ + b) * T_ * 64;
    float*       outp = g_qkv + ((size_t)j * B_ + b) * T_ * 16 + jh;

    float h = 0.0f, c = 0.0f;
    int srcbase = lane & 16;
    float n0 = xgp[jh], n1 = xgp[16 + jh], n2 = xgp[32 + jh], n3 = xgp[48 + jh];
    for (int t = 0; t < T_; ++t) {
        float a0 = n0, a1 = n1, a2 = n2, a3 = n3;
        if (t + 1 < T_) {
            const float* p = xgp + (t + 1) * 64;
            n0 = p[jh]; n1 = p[16 + jh]; n2 = p[32 + jh]; n3 = p[48 + jh];
        }
#pragma unroll
        for (int k = 0; k < 16; k++) {
            float hk = __shfl_sync(FULLMASK, h, srcbase + k);
            a0 = fmaf(wr[0][k], hk, a0);
            a1 = fmaf(wr[1][k], hk, a1);
            a2 = fmaf(wr[2][k], hk, a2);
            a3 = fmaf(wr[3][k], hk, a3);
        }
        c = sigf(a1) * c + sigf(a0) * tanhf_(a2);
        h = sigf(a3) * tanhf_(c);
        outp[t * 16] = h;
    }
}

// ---------------- kernel 4: triangular masked softmax attention, row-paired ------
// out[t] = (sum_{s<=t} e^{E_s} V_s + SufV[t]) / (sum_{s<=t} e^{E_s} + (199-t))
// Q prefetched to smem; merged fold-tree epilogue.
__global__ void __launch_bounds__(256, 2) k4_attn()
{
    __shared__ float Qs[200 * 16];
    __shared__ float Ks[224 * 20];     // rows 200..223 zero-filled
    __shared__ float Vs[224 * 20];
    __shared__ float Suf[200 * 16];
    __shared__ float Seg[8][16];

    int b  = blockIdx.x % 400;
    int br = blockIdx.x / 400;
    int tid = threadIdx.x;
    const float* qp = g_qkv + ((size_t)(br * 3 + 0) * B_ + b) * T_ * 16;
    const float* kp = g_qkv + ((size_t)(br * 3 + 1) * B_ + b) * T_ * 16;
    const float* vp = g_qkv + ((size_t)(br * 3 + 2) * B_ + b) * T_ * 16;

    for (int idx = tid; idx < 3200; idx += 256) {
        int t = idx >> 4, f = idx & 15;
        Qs[idx]        = qp[idx];
        Ks[t * 20 + f] = kp[idx];
        Vs[t * 20 + f] = vp[idx];
    }
    for (int idx = 3200 + tid; idx < 3584; idx += 256) {
        int t = idx >> 4, f = idx & 15;
        Ks[t * 20 + f] = 0.0f;
        Vs[t * 20 + f] = 0.0f;
    }
    __syncthreads();

    if (tid < 128) {
        int f = tid & 15, seg = tid >> 4;
        float s = 0.0f;
        for (int tt = 0; tt < 25; tt++) s += Vs[(seg * 25 + tt) * 20 + f];
        Seg[seg][f] = s;
    }
    __syncthreads();
    if (tid < 128) {
        int f = tid & 15, seg = tid >> 4;
        float run = 0.0f;
        for (int s2 = seg + 1; s2 < 8; s2++) run += Seg[s2][f];
        for (int tt = 24; tt >= 0; tt--) {
            int t = seg * 25 + tt;
            Suf[t * 16 + f] = run;
            run += Vs[t * 20 + f];
        }
    }
    __syncthreads();

    int warp = tid >> 5, lane = tid & 31;
    bool hi16 = (lane & 16) != 0;
    float* attp = g_att + ((size_t)br * B_ + b) * T_ * 16;

    for (int tp = warp; tp < 100; tp += 8) {
        int t0 = tp * 2, t1 = t0 + 1;
        const float4* q0r = (const float4*)&Qs[t0 * 16];
        const float4* q1r = (const float4*)&Qs[t1 * 16];
        float4 qa0 = q0r[0], qa1 = q0r[1], qa2 = q0r[2], qa3 = q0r[3];
        float4 qb0 = q1r[0], qb1 = q1r[1], qb2 = q1r[2], qb3 = q1r[3];

        float acc0[16], acc1[16];
#pragma unroll
        for (int f2 = 0; f2 < 16; f2++) { acc0[f2] = 0.0f; acc1[f2] = 0.0f; }
        float z0 = 0.0f, z1 = 0.0f;

        int nch = (t1 >> 5) + 1;
#pragma unroll
        for (int i = 0; i < 7; i++) {
            if (i < nch) {                        // warp-uniform
                int s = lane + (i << 5);
                const float4* kr = (const float4*)&Ks[s * 20];
                float4 k0 = kr[0], k1 = kr[1], k2 = kr[2], k3 = kr[3];
                float e0 = qa0.x*k0.x + qa0.y*k0.y + qa0.z*k0.z + qa0.w*k0.w
                         + qa1.x*k1.x + qa1.y*k1.y + qa1.z*k1.z + qa1.w*k1.w
                         + qa2.x*k2.x + qa2.y*k2.y + qa2.z*k2.z + qa2.w*k2.w
                         + qa3.x*k3.x + qa3.y*k3.y + qa3.z*k3.z + qa3.w*k3.w;
                float e1 = qb0.x*k0.x + qb0.y*k0.y + qb0.z*k0.z + qb0.w*k0.w
                         + qb1.x*k1.x + qb1.y*k1.y + qb1.z*k1.z + qb1.w*k1.w
                         + qb2.x*k2.x + qb2.y*k2.y + qb2.z*k2.z + qb2.w*k2.w
                         + qb3.x*k3.x + qb3.y*k3.y + qb3.z*k3.z + qb3.w*k3.w;
                float p0 = (s <= t0) ? __expf(e0 * 0.25f) : 0.0f;
                float p1 = (s <= t1) ? __expf(e1 * 0.25f) : 0.0f;
                z0 += p0; z1 += p1;
                const float4* vr = (const float4*)&Vs[s * 20];
                float4 v0 = vr[0], v1 = vr[1], v2 = vr[2], v3 = vr[3];
                acc0[0]  = fmaf(p0, v0.x, acc0[0]);  acc1[0]  = fmaf(p1, v0.x, acc1[0]);
                acc0[1]  = fmaf(p0, v0.y, acc0[1]);  acc1[1]  = fmaf(p1, v0.y, acc1[1]);
                acc0[2]  = fmaf(p0, v0.z, acc0[2]);  acc1[2]  = fmaf(p1, v0.z, acc1[2]);
                acc0[3]  = fmaf(p0, v0.w, acc0[3]);  acc1[3]  = fmaf(p1, v0.w, acc1[3]);
                acc0[4]  = fmaf(p0, v1.x, acc0[4]);  acc1[4]  = fmaf(p1, v1.x, acc1[4]);
                acc0[5]  = fmaf(p0, v1.y, acc0[5]);  acc1[5]  = fmaf(p1, v1.y, acc1[5]);
                acc0[6]  = fmaf(p0, v1.z, acc0[6]);  acc1[6]  = fmaf(p1, v1.z, acc1[6]);
                acc0[7]  = fmaf(p0, v1.w, acc0[7]);  acc1[7]  = fmaf(p1, v1.w, acc1[7]);
                acc0[8]  = fmaf(p0, v2.x, acc0[8]);  acc1[8]  = fmaf(p1, v2.x, acc1[8]);
                acc0[9]  = fmaf(p0, v2.y, acc0[9]);  acc1[9]  = fmaf(p1, v2.y, acc1[9]);
                acc0[10] = fmaf(p0, v2.z, acc0[10]); acc1[10] = fmaf(p1, v2.z, acc1[10]);
                acc0[11] = fmaf(p0, v2.w, acc0[11]); acc1[11] = fmaf(p1, v2.w, acc1[11]);
                acc0[12] = fmaf(p0, v3.x, acc0[12]); acc1[12] = fmaf(p1, v3.x, acc1[12]);
                acc0[13] = fmaf(p0, v3.y, acc0[13]); acc1[13] = fmaf(p1, v3.y, acc1[13]);
                acc0[14] = fmaf(p0, v3.z, acc0[14]); acc1[14] = fmaf(p1, v3.z, acc1[14]);
                acc0[15] = fmaf(p0, v3.w, acc0[15]); acc1[15] = fmaf(p1, v3.w, acc1[15]);
            }
        }

        float zz;
        {
            float zm = hi16 ? z1 : z0;
            float zo = hi16 ? z0 : z1;
            zz = zm + __shfl_xor_sync(FULLMASK, zo, 16);
#pragma unroll
            for (int off = 8; off; off >>= 1) zz += __shfl_xor_sync(FULLMASK, zz, off);
        }

        float m16[16];
#pragma unroll
        for (int f2 = 0; f2 < 16; f2++) {
            float mine = hi16 ? acc1[f2] : acc0[f2];
            float send = hi16 ? acc0[f2] : acc1[f2];
            m16[f2] = mine + __shfl_xor_sync(FULLMASK, send, 16);
        }
        float r8[8];
        {
            bool hi = (lane & 8) != 0;
#pragma unroll
            for (int f2 = 0; f2 < 8; f2++) {
                float keep = hi ? m16[f2 + 8] : m16[f2];
                float send = hi ? m16[f2]     : m16[f2 + 8];
                r8[f2] = keep + __shfl_xor_sync(FULLMASK, send, 8);
            }
        }
        float r4[4];
        {
            bool hi = (lane & 4) != 0;
#pragma unroll
            for (int f2 = 0; f2 < 4; f2++) {
                float keep = hi ? r8[f2 + 4] : r8[f2];
                float send = hi ? r8[f2]     : r8[f2 + 4];
                r4[f2] = keep + __shfl_xor_sync(FULLMASK, send, 4);
            }
        }
        float r2[2];
        {
            bool hi = (lane & 2) != 0;
#pragma unroll
            for (int f2 = 0; f2 < 2; f2++) {
                float keep = hi ? r4[f2 + 2] : r4[f2];
                float send = hi ? r4[f2]     : r4[f2 + 2];
                r2[f2] = keep + __shfl_xor_sync(FULLMASK, send, 2);
            }
        }
        float r1;
        {
            bool hi = (lane & 1) != 0;
            float keep = hi ? r2[1] : r2[0];
            float send = hi ? r2[0] : r2[1];
            r1 = keep + __shfl_xor_sync(FULLMASK, send, 1);
        }

        int f = lane & 15;
        int t = hi16 ? t1 : t0;
        float Z = zz + (float)(199 - t);
        attp[t * 16 + f] = (r1 + Suf[t * 16 + f]) / Z;
    }
}

// ---------------- kernel 5: combine + LN2 + complex linear + LN3 + PReLU + res --
__global__ void k5_final(const float* __restrict__ inp,
                         const float* __restrict__ ln2w, const float* __restrict__ ln2b,
                         const float* __restrict__ lrw,  const float* __restrict__ lrb,
                         const float* __restrict__ liw,  const float* __restrict__ lib,
                         const float* __restrict__ ln3w, const float* __restrict__ ln3b,
                         const float* __restrict__ pa,   float* __restrict__ out)
{
    __shared__ __align__(16) float zs[64][84];
    int bid = blockIdx.x;
    int tile = bid % 5, nf = bid / 5;
    int n = nf / 100, f = nf % 100;
    int t0 = tile * 40;
    int tid = threadIdx.x;
    int lane = tid & 31, warp = tid >> 5;
    int c0 = lane, c1 = lane + 32;

    float Wr0[16], Wi0[16], Wr1[16], Wi1[16];
#pragma unroll
    for (int k = 0; k < 16; k++) {
        Wr0[k] = lrw[c0 * 16 + k]; Wi0[k] = liw[c0 * 16 + k];
        Wr1[k] = lrw[c1 * 16 + k]; Wi1[k] = liw[c1 * 16 + k];
    }
    float br0 = lrb[c0], br1 = lrb[c1], bi0 = lib[c0], bi1 = lib[c1];
    float w3_0 = ln3w[c0], w3_1 = ln3w[c1], b3_0 = ln3b[c0], b3_1 = ln3b[c1];
    int fh = lane & 15;
    float w2 = ln2w[fh], b2 = ln2b[fh];
    float a = pa[0];
    const size_t bs = (size_t)B_ * T_ * 16;
    int b = nf;

#pragma unroll
    for (int kk = 0; kk < 5; kk++) {
        int tt = warp + kk * 8;
        int t = t0 + tt;

        int brb = (lane < 16) ? 0 : 4;
        const float* ap = g_att + (size_t)brb * bs + ((size_t)b * T_ + t) * 16 + fh;
        float a0 = ap[0], a1 = ap[bs], a2 = ap[2 * bs], a3 = ap[3 * bs];
        float val = (lane < 16) ? (a0 - a1 - a2 - a3) : (a0 + a1 + a2 - a3);

        float s = val, ss = val * val;
#pragma unroll
        for (int off = 8; off; off >>= 1) {
            s  += __shfl_xor_sync(FULLMASK, s,  off);
            ss += __shfl_xor_sync(FULLMASK, ss, off);
        }
        float mean = s * (1.0f / 16.0f);
        float rs = rsqrtf(ss * (1.0f / 16.0f) - mean * mean + 1e-5f);
        float y = (val - mean) * rs * w2 + b2;

        float or0 = br0 - bi0, or1 = br1 - bi1, oi0 = br0 + bi0, oi1 = br1 + bi1;
#pragma unroll
        for (int k = 0; k < 16; k++) {
            float xr = __shfl_sync(FULLMASK, y, k);
            float xi = __shfl_sync(FULLMASK, y, 16 + k);
            or0 = fmaf(Wr0[k], xr, or0); or0 = fmaf(-Wi0[k], xi, or0);
            oi0 = fmaf(Wr0[k], xi, oi0); oi0 = fmaf( Wi0[k], xr, oi0);
            or1 = fmaf(Wr1[k], xr, or1); or1 = fmaf(-Wi1[k], xi, or1);
            oi1 = fmaf(Wr1[k], xi, oi1); oi1 = fmaf( Wi1[k], xr, oi1);
        }

        float sr = or0 + or1, sqr = or0 * or0 + or1 * or1;
        float si = oi0 + oi1, sqi = oi0 * oi0 + oi1 * oi1;
#pragma unroll
        for (int off = 16; off; off >>= 1) {
            sr  += __shfl_xor_sync(FULLMASK, sr,  off);
            sqr += __shfl_xor_sync(FULLMASK, sqr, off);
            si  += __shfl_xor_sync(FULLMASK, si,  off);
            sqi += __shfl_xor_sync(FULLMASK, sqi, off);
        }
        float mr = sr * (1.0f / 64.0f), mi = si * (1.0f / 64.0f);
        float rr  = rsqrtf(sqr * (1.0f / 64.0f) - mr * mr + 1e-5f);
        float rim = rsqrtf(sqi * (1.0f / 64.0f) - mi * mi + 1e-5f);
        float zr0 = (or0 - mr) * rr  * w3_0 + b3_0;
        float zr1 = (or1 - mr) * rr  * w3_1 + b3_1;
        float zi0 = (oi0 - mi) * rim * w3_0 + b3_0;
        float zi1 = (oi1 - mi) * rim * w3_1 + b3_1;
        zr0 = zr0 >= 0.0f ? zr0 : a * zr0;
        zr1 = zr1 >= 0.0f ? zr1 : a * zr1;
        zi0 = zi0 >= 0.0f ? zi0 : a * zi0;
        zi1 = zi1 >= 0.0f ? zi1 : a * zi1;

        zs[c0][tt * 2 + 0] = zr0;
        zs[c0][tt * 2 + 1] = zi0;
        zs[c1][tt * 2 + 0] = zr1;
        zs[c1][tt * 2 + 1] = zi1;
    }
    __syncthreads();

#pragma unroll
    for (int it = 0; it < 5; it++) {
        int idx = it * 256 + tid;
        int c = idx / 20, part = idx % 20;
        size_t g = ((size_t)(n * 64 + c) * 100 + f) * 400 + (size_t)t0 * 2 + part * 4;
        float4 z = *(float4*)&zs[c][part * 4];
        float4 iv = *(const float4*)(inp + g);
        z.x += iv.x; z.y += iv.y; z.z += iv.z; z.w += iv.w;
        *(float4*)(out + g) = z;
    }
}

// ---------------- launch ---------------------------------------------------------
extern "C" void kernel_launch(void* const* d_in, const int* in_sizes, int n_in,
                              void* d_out, int out_size)
{
    const float* inp    = (const float*)d_in[0];
    const float* Wih    = (const float*)d_in[1];
    const float* Whh    = (const float*)d_in[2];
    const float* bih    = (const float*)d_in[3];
    const float* bhh    = (const float*)d_in[4];
    const float* ln1w   = (const float*)d_in[5];
    const float* ln1b   = (const float*)d_in[6];
    const float* ln2w   = (const float*)d_in[7];
    const float* ln2b   = (const float*)d_in[8];
    const float* lrw    = (const float*)d_in[9];
    const float* lrb    = (const float*)d_in[10];
    const float* liw    = (const float*)d_in[11];
    const float* lib    = (const float*)d_in[12];
    const float* ln3w   = (const float*)d_in[13];
    const float* ln3b   = (const float*)d_in[14];
    const float* prelua = (const float*)d_in[15];
    float* out = (float*)d_out;

    k1_ln1<<<2000, 256>>>(inp, ln1w, ln1b);
    dim3 g2(125, 24);
    for (int c = 0; c < 5; c++) {
        int b0c = c * BC_;
        k2_gemm<<<g2, 256>>>(Wih, bih, bhh, b0c);
        k3_lstm<<<240, 128>>>(Whh, b0c);
    }
    k4_attn<<<3200, 256>>>();
    k5_final<<<2000, 256>>>(inp, ln2w, ln2b, lrw, lrb, liw, lib, ln3w, ln3b, prelua, out);
}

// round 13
// speedup vs baseline: 1.3656x; 1.3656x over previous
#include <cuda_runtime.h>
#include <math.h>
#include <stdint.h>

#define FULLMASK 0xffffffffu

constexpr int N_ = 4, C_ = 64, F_ = 100, T_ = 200, H_ = 16;
constexpr int B_  = N_ * F_;        // 400
constexpr int BT_ = B_ * T_;        // 80000
constexpr int NJ  = 24;             // 8 branches * 3 lstms

// ---------------- scratch (static device globals; no allocation) ----------------
__device__ float g_xln[(size_t)2 * BT_ * C_];        // [2][B][T][C]
__device__ float g_xg [(size_t)NJ * BT_ * C_];       // [24][B*T][64]
__device__ float g_qkv[(size_t)NJ * B_ * T_ * H_];   // [24][B][T][16]
__device__ float g_att[(size_t)8  * B_ * T_ * H_];   // [8][B][T][16]

__constant__ int SRC[24] = {0,0,0, 0,1,1, 1,0,1, 1,1,0, 0,0,1, 0,1,0, 1,0,0, 1,1,1};

__device__ __forceinline__ float sigf(float x)   { return 1.0f / (1.0f + __expf(-x)); }
__device__ __forceinline__ float tanhf_(float x) { return 2.0f / (1.0f + __expf(-2.0f * x)) - 1.0f; }

__device__ __forceinline__ uint32_t f2tf32(float x) {
    uint32_t r;
    asm("cvt.rna.tf32.f32 %0, %1;" : "=r"(r) : "f"(x));
    return r;
}

__device__ __forceinline__ void mma_tf32(float c[4],
                                         uint32_t a0, uint32_t a1, uint32_t a2, uint32_t a3,
                                         uint32_t b0, uint32_t b1) {
    asm volatile(
        "mma.sync.aligned.m16n8k8.row.col.f32.tf32.tf32.f32 "
        "{%0,%1,%2,%3}, {%4,%5,%6,%7}, {%8,%9}, {%0,%1,%2,%3};\n"
        : "+f"(c[0]), "+f"(c[1]), "+f"(c[2]), "+f"(c[3])
        : "r"(a0), "r"(a1), "r"(a2), "r"(a3), "r"(b0), "r"(b1));
}

// ---------------- kernel 1: permute + LayerNorm1 (coalesced via smem transpose) --
__global__ void k1_ln1(const float* __restrict__ inp,
                       const float* __restrict__ w, const float* __restrict__ bb)
{
    __shared__ float xs[2][40][65];
    int bid = blockIdx.x;
    int tile = bid % 5, nf = bid / 5;
    int n = nf / 100, f = nf % 100;
    int t0 = tile * 40;
    int tid = threadIdx.x;

    int c = tid >> 2, q = tid & 3;
    const float* base = inp + ((size_t)(n * 64 + c) * 100 + f) * 400 + (size_t)t0 * 2;
#pragma unroll
    for (int i = 0; i < 10; i++) {
        int tt = q * 10 + i;
        float2 v = *(const float2*)(base + tt * 2);
        xs[0][tt][c] = v.x;
        xs[1][tt][c] = v.y;
    }
    __syncthreads();

    int warp = tid >> 5, lane = tid & 31;
    int c0 = lane, c1 = lane + 32;
    float w0 = w[c0], w1 = w[c1], b0 = bb[c0], b1 = bb[c1];

#pragma unroll
    for (int kk = 0; kk < 5; kk++) {
        int tt = warp + kk * 8;
        float vx0 = xs[0][tt][c0], vx1 = xs[0][tt][c1];
        float vy0 = xs[1][tt][c0], vy1 = xs[1][tt][c1];
        float sx = vx0 + vx1, sxx = vx0 * vx0 + vx1 * vx1;
        float sy = vy0 + vy1, syy = vy0 * vy0 + vy1 * vy1;
#pragma unroll
        for (int off = 16; off; off >>= 1) {
            sx  += __shfl_xor_sync(FULLMASK, sx,  off);
            sxx += __shfl_xor_sync(FULLMASK, sxx, off);
            sy  += __shfl_xor_sync(FULLMASK, sy,  off);
            syy += __shfl_xor_sync(FULLMASK, syy, off);
        }
        float mx = sx * (1.0f / 64.0f), my = sy * (1.0f / 64.0f);
        float rx = rsqrtf(sxx * (1.0f / 64.0f) - mx * mx + 1e-5f);
        float ry = rsqrtf(syy * (1.0f / 64.0f) - my * my + 1e-5f);
        int pos = nf * 200 + t0 + tt;
        float* o0 = g_xln + (size_t)pos * C_;
        float* o1 = g_xln + (size_t)BT_ * C_ + (size_t)pos * C_;
        o0[c0] = (vx0 - mx) * rx * w0 + b0;
        o0[c1] = (vx1 - mx) * rx * w1 + b1;
        o1[c0] = (vy0 - my) * ry * w0 + b0;
        o1[c1] = (vy1 - my) * ry * w1 + b1;
    }
}

// ---------------- kernel 2: xg = xln[src] @ Wih^T via tf32 MMA (2-term comp) ----
// monolithic grid (625, 24), 256 thr = 8 warps x 16 rows = 128-row tile, N=64.
// W pre-converted to tf32 at staging (no cvt in mainloop).
__global__ void __launch_bounds__(256) k2_gemm(const float* __restrict__ Wih,
                        const float* __restrict__ bih, const float* __restrict__ bhh)
{
    __shared__ float As[64][136];
    __shared__ uint32_t Ws[64][72];    // tf32-rounded bits
    int j   = blockIdx.y;
    int src = SRC[j];
    int bt0 = blockIdx.x * 128;
    int tid = threadIdx.x;

    const float* A = g_xln + (size_t)src * BT_ * C_ + (size_t)bt0 * C_;
    const float* W = Wih + (size_t)j * 4096;
#pragma unroll
    for (int it = 0; it < 32; ++it) {
        int idx = it * 256 + tid;
        int rr = idx >> 6, kk = idx & 63;
        As[kk][rr] = A[idx];
    }
#pragma unroll
    for (int it = 0; it < 16; ++it) {
        int idx = it * 256 + tid;
        int rr = idx >> 6, kk = idx & 63;
        Ws[kk][rr] = f2tf32(W[idx]);
    }
    __syncthreads();

    int warp = tid >> 5, lane = tid & 31;
    int grp = lane >> 2, tid4 = lane & 3;
    int rbase = warp * 16;

    float2 bv[8];
#pragma unroll
    for (int nb = 0; nb < 8; nb++) {
        int col = nb * 8 + tid4 * 2;
        bv[nb].x = bih[j * 64 + col]     + bhh[j * 64 + col];
        bv[nb].y = bih[j * 64 + col + 1] + bhh[j * 64 + col + 1];
    }

    float acc[8][4];
#pragma unroll
    for (int nb = 0; nb < 8; nb++)
#pragma unroll
        for (int x = 0; x < 4; x++) acc[nb][x] = 0.0f;

#pragma unroll
    for (int ks = 0; ks < 8; ks++) {
        int kc = ks * 8 + tid4;
        float a0f = As[kc][rbase + grp];
        float a1f = As[kc][rbase + grp + 8];
        float a2f = As[kc + 4][rbase + grp];
        float a3f = As[kc + 4][rbase + grp + 8];
        uint32_t a0h = f2tf32(a0f), a1h = f2tf32(a1f), a2h = f2tf32(a2f), a3h = f2tf32(a3f);
        uint32_t a0l = __float_as_uint(a0f - __uint_as_float(a0h));
        uint32_t a1l = __float_as_uint(a1f - __uint_as_float(a1h));
        uint32_t a2l = __float_as_uint(a2f - __uint_as_float(a2h));
        uint32_t a3l = __float_as_uint(a3f - __uint_as_float(a3h));
#pragma unroll
        for (int nb = 0; nb < 8; nb++) {
            uint32_t b0h = Ws[kc][nb * 8 + grp];
            uint32_t b1h = Ws[kc + 4][nb * 8 + grp];
            mma_tf32(acc[nb], a0h, a1h, a2h, a3h, b0h, b1h);
            mma_tf32(acc[nb], a0l, a1l, a2l, a3l, b0h, b1h);
        }
    }

    float* O = g_xg + (size_t)j * BT_ * 64 + (size_t)bt0 * 64;
    int row0 = rbase + grp, row1 = rbase + grp + 8;
#pragma unroll
    for (int nb = 0; nb < 8; nb++) {
        int col = nb * 8 + tid4 * 2;
        *(float2*)&O[row0 * 64 + col] = make_float2(acc[nb][0] + bv[nb].x, acc[nb][1] + bv[nb].y);
        *(float2*)&O[row1 * 64 + col] = make_float2(acc[nb][2] + bv[nb].x, acc[nb][3] + bv[nb].y);
    }
}

// ---------------- kernel 3: LSTM recurrence (monolithic, full parallelism) ------
__global__ void k3_lstm(const float* __restrict__ Whh)
{
    int gw   = blockIdx.x * 4 + (threadIdx.x >> 5);  // 0..4799
    int lane = threadIdx.x & 31;
    int j  = gw / 200;
    int bp = gw % 200;
    int seq = lane >> 4, jh = lane & 15;
    int b = bp * 2 + seq;

    float wr[4][16];
#pragma unroll
    for (int g = 0; g < 4; g++)
#pragma unroll
        for (int k = 0; k < 16; k++)
            wr[g][k] = Whh[j * 1024 + (g * 16 + jh) * 16 + k];

    const float* xgp  = g_xg  + ((size_t)j * B_ + b) * T_ * 64;
    float*       outp = g_qkv + ((size_t)j * B_ + b) * T_ * 16 + jh;

    float h = 0.0f, c = 0.0f;
    int srcbase = lane & 16;
    float n0 = xgp[jh], n1 = xgp[16 + jh], n2 = xgp[32 + jh], n3 = xgp[48 + jh];
    for (int t = 0; t < T_; ++t) {
        float a0 = n0, a1 = n1, a2 = n2, a3 = n3;
        if (t + 1 < T_) {
            const float* p = xgp + (t + 1) * 64;
            n0 = p[jh]; n1 = p[16 + jh]; n2 = p[32 + jh]; n3 = p[48 + jh];
        }
#pragma unroll
        for (int k = 0; k < 16; k++) {
            float hk = __shfl_sync(FULLMASK, h, srcbase + k);
            a0 = fmaf(wr[0][k], hk, a0);
            a1 = fmaf(wr[1][k], hk, a1);
            a2 = fmaf(wr[2][k], hk, a2);
            a3 = fmaf(wr[3][k], hk, a3);
        }
        c = sigf(a1) * c + sigf(a0) * tanhf_(a2);
        h = sigf(a3) * tanhf_(c);
        outp[t * 16] = h;
    }
}

// ---------------- kernel 4: triangular masked softmax attention, row-paired ------
// out[t] = (sum_{s<=t} e^{E_s} V_s + SufV[t]) / (sum_{s<=t} e^{E_s} + (199-t))
// Q prefetched to smem; merged fold-tree epilogue.
__global__ void __launch_bounds__(256, 2) k4_attn()
{
    __shared__ float Qs[200 * 16];
    __shared__ float Ks[224 * 20];     // rows 200..223 zero-filled
    __shared__ float Vs[224 * 20];
    __shared__ float Suf[200 * 16];
    __shared__ float Seg[8][16];

    int b  = blockIdx.x % 400;
    int br = blockIdx.x / 400;
    int tid = threadIdx.x;
    const float* qp = g_qkv + ((size_t)(br * 3 + 0) * B_ + b) * T_ * 16;
    const float* kp = g_qkv + ((size_t)(br * 3 + 1) * B_ + b) * T_ * 16;
    const float* vp = g_qkv + ((size_t)(br * 3 + 2) * B_ + b) * T_ * 16;

    for (int idx = tid; idx < 3200; idx += 256) {
        int t = idx >> 4, f = idx & 15;
        Qs[idx]        = qp[idx];
        Ks[t * 20 + f] = kp[idx];
        Vs[t * 20 + f] = vp[idx];
    }
    for (int idx = 3200 + tid; idx < 3584; idx += 256) {
        int t = idx >> 4, f = idx & 15;
        Ks[t * 20 + f] = 0.0f;
        Vs[t * 20 + f] = 0.0f;
    }
    __syncthreads();

    if (tid < 128) {
        int f = tid & 15, seg = tid >> 4;
        float s = 0.0f;
        for (int tt = 0; tt < 25; tt++) s += Vs[(seg * 25 + tt) * 20 + f];
        Seg[seg][f] = s;
    }
    __syncthreads();
    if (tid < 128) {
        int f = tid & 15, seg = tid >> 4;
        float run = 0.0f;
        for (int s2 = seg + 1; s2 < 8; s2++) run += Seg[s2][f];
        for (int tt = 24; tt >= 0; tt--) {
            int t = seg * 25 + tt;
            Suf[t * 16 + f] = run;
            run += Vs[t * 20 + f];
        }
    }
    __syncthreads();

    int warp = tid >> 5, lane = tid & 31;
    bool hi16 = (lane & 16) != 0;
    float* attp = g_att + ((size_t)br * B_ + b) * T_ * 16;

    for (int tp = warp; tp < 100; tp += 8) {
        int t0 = tp * 2, t1 = t0 + 1;
        const float4* q0r = (const float4*)&Qs[t0 * 16];
        const float4* q1r = (const float4*)&Qs[t1 * 16];
        float4 qa0 = q0r[0], qa1 = q0r[1], qa2 = q0r[2], qa3 = q0r[3];
        float4 qb0 = q1r[0], qb1 = q1r[1], qb2 = q1r[2], qb3 = q1r[3];

        float acc0[16], acc1[16];
#pragma unroll
        for (int f2 = 0; f2 < 16; f2++) { acc0[f2] = 0.0f; acc1[f2] = 0.0f; }
        float z0 = 0.0f, z1 = 0.0f;

        int nch = (t1 >> 5) + 1;
#pragma unroll
        for (int i = 0; i < 7; i++) {
            if (i < nch) {                        // warp-uniform
                int s = lane + (i << 5);
                const float4* kr = (const float4*)&Ks[s * 20];
                float4 k0 = kr[0], k1 = kr[1], k2 = kr[2], k3 = kr[3];
                float e0 = qa0.x*k0.x + qa0.y*k0.y + qa0.z*k0.z + qa0.w*k0.w
                         + qa1.x*k1.x + qa1.y*k1.y + qa1.z*k1.z + qa1.w*k1.w
                         + qa2.x*k2.x + qa2.y*k2.y + qa2.z*k2.z + qa2.w*k2.w
                         + qa3.x*k3.x + qa3.y*k3.y + qa3.z*k3.z + qa3.w*k3.w;
                float e1 = qb0.x*k0.x + qb0.y*k0.y + qb0.z*k0.z + qb0.w*k0.w
                         + qb1.x*k1.x + qb1.y*k1.y + qb1.z*k1.z + qb1.w*k1.w
                         + qb2.x*k2.x + qb2.y*k2.y + qb2.z*k2.z + qb2.w*k2.w
                         + qb3.x*k3.x + qb3.y*k3.y + qb3.z*k3.z + qb3.w*k3.w;
                float p0 = (s <= t0) ? __expf(e0 * 0.25f) : 0.0f;
                float p1 = (s <= t1) ? __expf(e1 * 0.25f) : 0.0f;
                z0 += p0; z1 += p1;
                const float4* vr = (const float4*)&Vs[s * 20];
                float4 v0 = vr[0], v1 = vr[1], v2 = vr[2], v3 = vr[3];
                acc0[0]  = fmaf(p0, v0.x, acc0[0]);  acc1[0]  = fmaf(p1, v0.x, acc1[0]);
                acc0[1]  = fmaf(p0, v0.y, acc0[1]);  acc1[1]  = fmaf(p1, v0.y, acc1[1]);
                acc0[2]  = fmaf(p0, v0.z, acc0[2]);  acc1[2]  = fmaf(p1, v0.z, acc1[2]);
                acc0[3]  = fmaf(p0, v0.w, acc0[3]);  acc1[3]  = fmaf(p1, v0.w, acc1[3]);
                acc0[4]  = fmaf(p0, v1.x, acc0[4]);  acc1[4]  = fmaf(p1, v1.x, acc1[4]);
                acc0[5]  = fmaf(p0, v1.y, acc0[5]);  acc1[5]  = fmaf(p1, v1.y, acc1[5]);
                acc0[6]  = fmaf(p0, v1.z, acc0[6]);  acc1[6]  = fmaf(p1, v1.z, acc1[6]);
                acc0[7]  = fmaf(p0, v1.w, acc0[7]);  acc1[7]  = fmaf(p1, v1.w, acc1[7]);
                acc0[8]  = fmaf(p0, v2.x, acc0[8]);  acc1[8]  = fmaf(p1, v2.x, acc1[8]);
                acc0[9]  = fmaf(p0, v2.y, acc0[9]);  acc1[9]  = fmaf(p1, v2.y, acc1[9]);
                acc0[10] = fmaf(p0, v2.z, acc0[10]); acc1[10] = fmaf(p1, v2.z, acc1[10]);
                acc0[11] = fmaf(p0, v2.w, acc0[11]); acc1[11] = fmaf(p1, v2.w, acc1[11]);
                acc0[12] = fmaf(p0, v3.x, acc0[12]); acc1[12] = fmaf(p1, v3.x, acc1[12]);
                acc0[13] = fmaf(p0, v3.y, acc0[13]); acc1[13] = fmaf(p1, v3.y, acc1[13]);
                acc0[14] = fmaf(p0, v3.z, acc0[14]); acc1[14] = fmaf(p1, v3.z, acc1[14]);
                acc0[15] = fmaf(p0, v3.w, acc0[15]); acc1[15] = fmaf(p1, v3.w, acc1[15]);
            }
        }

        float zz;
        {
            float zm = hi16 ? z1 : z0;
            float zo = hi16 ? z0 : z1;
            zz = zm + __shfl_xor_sync(FULLMASK, zo, 16);
#pragma unroll
            for (int off = 8; off; off >>= 1) zz += __shfl_xor_sync(FULLMASK, zz, off);
        }

        float m16[16];
#pragma unroll
        for (int f2 = 0; f2 < 16; f2++) {
            float mine = hi16 ? acc1[f2] : acc0[f2];
            float send = hi16 ? acc0[f2] : acc1[f2];
            m16[f2] = mine + __shfl_xor_sync(FULLMASK, send, 16);
        }
        float r8[8];
        {
            bool hi = (lane & 8) != 0;
#pragma unroll
            for (int f2 = 0; f2 < 8; f2++) {
                float keep = hi ? m16[f2 + 8] : m16[f2];
                float send = hi ? m16[f2]     : m16[f2 + 8];
                r8[f2] = keep + __shfl_xor_sync(FULLMASK, send, 8);
            }
        }
        float r4[4];
        {
            bool hi = (lane & 4) != 0;
#pragma unroll
            for (int f2 = 0; f2 < 4; f2++) {
                float keep = hi ? r8[f2 + 4] : r8[f2];
                float send = hi ? r8[f2]     : r8[f2 + 4];
                r4[f2] = keep + __shfl_xor_sync(FULLMASK, send, 4);
            }
        }
        float r2[2];
        {
            bool hi = (lane & 2) != 0;
#pragma unroll
            for (int f2 = 0; f2 < 2; f2++) {
                float keep = hi ? r4[f2 + 2] : r4[f2];
                float send = hi ? r4[f2]     : r4[f2 + 2];
                r2[f2] = keep + __shfl_xor_sync(FULLMASK, send, 2);
            }
        }
        float r1;
        {
            bool hi = (lane & 1) != 0;
            float keep = hi ? r2[1] : r2[0];
            float send = hi ? r2[0] : r2[1];
            r1 = keep + __shfl_xor_sync(FULLMASK, send, 1);
        }

        int f = lane & 15;
        int t = hi16 ? t1 : t0;
        float Z = zz + (float)(199 - t);
        attp[t * 16 + f] = (r1 + Suf[t * 16 + f]) / Z;
    }
}

// ---------------- kernel 5: combine + LN2 + complex linear + LN3 + PReLU + res --
__global__ void k5_final(const float* __restrict__ inp,
                         const float* __restrict__ ln2w, const float* __restrict__ ln2b,
                         const float* __restrict__ lrw,  const float* __restrict__ lrb,
                         const float* __restrict__ liw,  const float* __restrict__ lib,
                         const float* __restrict__ ln3w, const float* __restrict__ ln3b,
                         const float* __restrict__ pa,   float* __restrict__ out)
{
    __shared__ __align__(16) float zs[64][84];
    int bid = blockIdx.x;
    int tile = bid % 5, nf = bid / 5;
    int n = nf / 100, f = nf % 100;
    int t0 = tile * 40;
    int tid = threadIdx.x;
    int lane = tid & 31, warp = tid >> 5;
    int c0 = lane, c1 = lane + 32;

    float Wr0[16], Wi0[16], Wr1[16], Wi1[16];
#pragma unroll
    for (int k = 0; k < 16; k++) {
        Wr0[k] = lrw[c0 * 16 + k]; Wi0[k] = liw[c0 * 16 + k];
        Wr1[k] = lrw[c1 * 16 + k]; Wi1[k] = liw[c1 * 16 + k];
    }
    float br0 = lrb[c0], br1 = lrb[c1], bi0 = lib[c0], bi1 = lib[c1];
    float w3_0 = ln3w[c0], w3_1 = ln3w[c1], b3_0 = ln3b[c0], b3_1 = ln3b[c1];
    int fh = lane & 15;
    float w2 = ln2w[fh], b2 = ln2b[fh];
    float a = pa[0];
    const size_t bs = (size_t)B_ * T_ * 16;
    int b = nf;

#pragma unroll
    for (int kk = 0; kk < 5; kk++) {
        int tt = warp + kk * 8;
        int t = t0 + tt;

        int brb = (lane < 16) ? 0 : 4;
        const float* ap = g_att + (size_t)brb * bs + ((size_t)b * T_ + t) * 16 + fh;
        float a0 = ap[0], a1 = ap[bs], a2 = ap[2 * bs], a3 = ap[3 * bs];
        float val = (lane < 16) ? (a0 - a1 - a2 - a3) : (a0 + a1 + a2 - a3);

        float s = val, ss = val * val;
#pragma unroll
        for (int off = 8; off; off >>= 1) {
            s  += __shfl_xor_sync(FULLMASK, s,  off);
            ss += __shfl_xor_sync(FULLMASK, ss, off);
        }
        float mean = s * (1.0f / 16.0f);
        float rs = rsqrtf(ss * (1.0f / 16.0f) - mean * mean + 1e-5f);
        float y = (val - mean) * rs * w2 + b2;

        float or0 = br0 - bi0, or1 = br1 - bi1, oi0 = br0 + bi0, oi1 = br1 + bi1;
#pragma unroll
        for (int k = 0; k < 16; k++) {
            float xr = __shfl_sync(FULLMASK, y, k);
            float xi = __shfl_sync(FULLMASK, y, 16 + k);
            or0 = fmaf(Wr0[k], xr, or0); or0 = fmaf(-Wi0[k], xi, or0);
            oi0 = fmaf(Wr0[k], xi, oi0); oi0 = fmaf( Wi0[k], xr, oi0);
            or1 = fmaf(Wr1[k], xr, or1); or1 = fmaf(-Wi1[k], xi, or1);
            oi1 = fmaf(Wr1[k], xi, oi1); oi1 = fmaf( Wi1[k], xr, oi1);
        }

        float sr = or0 + or1, sqr = or0 * or0 + or1 * or1;
        float si = oi0 + oi1, sqi = oi0 * oi0 + oi1 * oi1;
#pragma unroll
        for (int off = 16; off; off >>= 1) {
            sr  += __shfl_xor_sync(FULLMASK, sr,  off);
            sqr += __shfl_xor_sync(FULLMASK, sqr, off);
            si  += __shfl_xor_sync(FULLMASK, si,  off);
            sqi += __shfl_xor_sync(FULLMASK, sqi, off);
        }
        float mr = sr * (1.0f / 64.0f), mi = si * (1.0f / 64.0f);
        float rr  = rsqrtf(sqr * (1.0f / 64.0f) - mr * mr + 1e-5f);
        float rim = rsqrtf(sqi * (1.0f / 64.0f) - mi * mi + 1e-5f);
        float zr0 = (or0 - mr) * rr  * w3_0 + b3_0;
        float zr1 = (or1 - mr) * rr  * w3_1 + b3_1;
        float zi0 = (oi0 - mi) * rim * w3_0 + b3_0;
        float zi1 = (oi1 - mi) * rim * w3_1 + b3_1;
        zr0 = zr0 >= 0.0f ? zr0 : a * zr0;
        zr1 = zr1 >= 0.0f ? zr1 : a * zr1;
        zi0 = zi0 >= 0.0f ? zi0 : a * zi0;
        zi1 = zi1 >= 0.0f ? zi1 : a * zi1;

        zs[c0][tt * 2 + 0] = zr0;
        zs[c0][tt * 2 + 1] = zi0;
        zs[c1][tt * 2 + 0] = zr1;
        zs[c1][tt * 2 + 1] = zi1;
    }
    __syncthreads();

#pragma unroll
    for (int it = 0; it < 5; it++) {
        int idx = it * 256 + tid;
        int c = idx / 20, part = idx % 20;
        size_t g = ((size_t)(n * 64 + c) * 100 + f) * 400 + (size_t)t0 * 2 + part * 4;
        float4 z = *(float4*)&zs[c][part * 4];
        float4 iv = *(const float4*)(inp + g);
        z.x += iv.x; z.y += iv.y; z.z += iv.z; z.w += iv.w;
        *(float4*)(out + g) = z;
    }
}

// ---------------- launch ---------------------------------------------------------
extern "C" void kernel_launch(void* const* d_in, const int* in_sizes, int n_in,
                              void* d_out, int out_size)
{
    const float* inp    = (const float*)d_in[0];
    const float* Wih    = (const float*)d_in[1];
    const float* Whh    = (const float*)d_in[2];
    const float* bih    = (const float*)d_in[3];
    const float* bhh    = (const float*)d_in[4];
    const float* ln1w   = (const float*)d_in[5];
    const float* ln1b   = (const float*)d_in[6];
    const float* ln2w   = (const float*)d_in[7];
    const float* ln2b   = (const float*)d_in[8];
    const float* lrw    = (const float*)d_in[9];
    const float* lrb    = (const float*)d_in[10];
    const float* liw    = (const float*)d_in[11];
    const float* lib    = (const float*)d_in[12];
    const float* ln3w   = (const float*)d_in[13];
    const float* ln3b   = (const float*)d_in[14];
    const float* prelua = (const float*)d_in[15];
    float* out = (float*)d_out;

    k1_ln1<<<2000, 256>>>(inp, ln1w, ln1b);
    dim3 g2(625, 24);
    k2_gemm<<<g2, 256>>>(Wih, bih, bhh);
    k3_lstm<<<1200, 128>>>(Whh);
    k4_attn<<<3200, 256>>>();
    k5_final<<<2000, 256>>>(inp, ln2w, ln2b, lrw, lrb, liw, lib, ln3w, ln3b, prelua, out);
}

// round 14
// speedup vs baseline: 1.4775x; 1.0820x over previous
#include <cuda_runtime.h>
#include <math.h>
#include <stdint.h>

#define FULLMASK 0xffffffffu

constexpr int N_ = 4, C_ = 64, F_ = 100, T_ = 200, H_ = 16;
constexpr int B_  = N_ * F_;        // 400
constexpr int BT_ = B_ * T_;        // 80000
constexpr int NJ  = 24;             // 8 branches * 3 lstms

// ---------------- scratch (static device globals; no allocation) ----------------
__device__ float g_xln[(size_t)2 * BT_ * C_];        // [2][B][T][C]
__device__ float g_xg [(size_t)NJ * BT_ * C_];       // [24][B*T][64]
__device__ float g_qkv[(size_t)NJ * B_ * T_ * H_];   // [24][B][T][16]
__device__ float g_att[(size_t)8  * B_ * T_ * H_];   // [8][B][T][16]

__constant__ int SRC[24] = {0,0,0, 0,1,1, 1,0,1, 1,1,0, 0,0,1, 0,1,0, 1,0,0, 1,1,1};

__device__ __forceinline__ float sigf(float x)   { return 1.0f / (1.0f + __expf(-x)); }
__device__ __forceinline__ float tanhf_(float x) { return 2.0f / (1.0f + __expf(-2.0f * x)) - 1.0f; }

__device__ __forceinline__ uint32_t f2tf32(float x) {
    uint32_t r;
    asm("cvt.rna.tf32.f32 %0, %1;" : "=r"(r) : "f"(x));
    return r;
}

__device__ __forceinline__ void mma_tf32(float c[4],
                                         uint32_t a0, uint32_t a1, uint32_t a2, uint32_t a3,
                                         uint32_t b0, uint32_t b1) {
    asm volatile(
        "mma.sync.aligned.m16n8k8.row.col.f32.tf32.tf32.f32 "
        "{%0,%1,%2,%3}, {%4,%5,%6,%7}, {%8,%9}, {%0,%1,%2,%3};\n"
        : "+f"(c[0]), "+f"(c[1]), "+f"(c[2]), "+f"(c[3])
        : "r"(a0), "r"(a1), "r"(a2), "r"(a3), "r"(b0), "r"(b1));
}

// ---------------- kernel 1: permute + LayerNorm1 (coalesced via smem transpose) --
__global__ void k1_ln1(const float* __restrict__ inp,
                       const float* __restrict__ w, const float* __restrict__ bb)
{
    __shared__ float xs[2][40][65];
    int bid = blockIdx.x;
    int tile = bid % 5, nf = bid / 5;
    int n = nf / 100, f = nf % 100;
    int t0 = tile * 40;
    int tid = threadIdx.x;

    int c = tid >> 2, q = tid & 3;
    const float* base = inp + ((size_t)(n * 64 + c) * 100 + f) * 400 + (size_t)t0 * 2;
#pragma unroll
    for (int i = 0; i < 10; i++) {
        int tt = q * 10 + i;
        float2 v = *(const float2*)(base + tt * 2);
        xs[0][tt][c] = v.x;
        xs[1][tt][c] = v.y;
    }
    __syncthreads();

    int warp = tid >> 5, lane = tid & 31;
    int c0 = lane, c1 = lane + 32;
    float w0 = w[c0], w1 = w[c1], b0 = bb[c0], b1 = bb[c1];

#pragma unroll
    for (int kk = 0; kk < 5; kk++) {
        int tt = warp + kk * 8;
        float vx0 = xs[0][tt][c0], vx1 = xs[0][tt][c1];
        float vy0 = xs[1][tt][c0], vy1 = xs[1][tt][c1];
        float sx = vx0 + vx1, sxx = vx0 * vx0 + vx1 * vx1;
        float sy = vy0 + vy1, syy = vy0 * vy0 + vy1 * vy1;
#pragma unroll
        for (int off = 16; off; off >>= 1) {
            sx  += __shfl_xor_sync(FULLMASK, sx,  off);
            sxx += __shfl_xor_sync(FULLMASK, sxx, off);
            sy  += __shfl_xor_sync(FULLMASK, sy,  off);
            syy += __shfl_xor_sync(FULLMASK, syy, off);
        }
        float mx = sx * (1.0f / 64.0f), my = sy * (1.0f / 64.0f);
        float rx = rsqrtf(sxx * (1.0f / 64.0f) - mx * mx + 1e-5f);
        float ry = rsqrtf(syy * (1.0f / 64.0f) - my * my + 1e-5f);
        int pos = nf * 200 + t0 + tt;
        float* o0 = g_xln + (size_t)pos * C_;
        float* o1 = g_xln + (size_t)BT_ * C_ + (size_t)pos * C_;
        o0[c0] = (vx0 - mx) * rx * w0 + b0;
        o0[c1] = (vx1 - mx) * rx * w1 + b1;
        o1[c0] = (vy0 - my) * ry * w0 + b0;
        o1[c1] = (vy1 - my) * ry * w1 + b1;
    }
}

// ---------------- kernel 2: xg = xln[src] @ Wih^T via tf32 MMA (2-term comp) ----
// grid (625, 24), 256 thr = 8 warps x 16 rows = 128-row tile, N=64.
// Fragment-major smem: A fragments read as LDS.128, W (pre-tf32) as LDS.64.
__global__ void __launch_bounds__(256) k2_gemm(const float* __restrict__ Wih,
                        const float* __restrict__ bih, const float* __restrict__ bhh)
{
    __shared__ __align__(16) float    AF[32 * 264];   // [plane=ks*4+tid4][warp*32+grp*4+slot]
    __shared__ __align__(8)  uint32_t WF[32 * 136];   // [plane][col*2+{0,1}] tf32 bits
    int j   = blockIdx.y;
    int src = SRC[j];
    int bt0 = blockIdx.x * 128;
    int tid = threadIdx.x;

    const float* A = g_xln + (size_t)src * BT_ * C_ + (size_t)bt0 * C_;
    const float* W = Wih + (size_t)j * 4096;

    // stage A into fragment-major layout
#pragma unroll
    for (int it = 0; it < 32; ++it) {
        int idx = it * 256 + tid;            // row*64 + k
        int row = idx >> 6, k = idx & 63;
        int ks = k >> 3, t4 = k & 3, khi = (k >> 2) & 1;
        int warp_i = row >> 4, within = row & 15;
        int grp_i = within & 7, half = within >> 3;
        int slot = khi * 2 + half;
        AF[(ks * 4 + t4) * 264 + warp_i * 32 + grp_i * 4 + slot] = A[idx];
    }
    // stage W (pre-converted tf32) into fragment-pair layout
#pragma unroll
    for (int it = 0; it < 16; ++it) {
        int idx = it * 256 + tid;            // g*64 + c
        int g = idx >> 6, c = idx & 63;
        int ks = c >> 3, t4 = c & 3, chi = (c >> 2) & 1;
        WF[(ks * 4 + t4) * 136 + g * 2 + chi] = f2tf32(W[idx]);
    }
    __syncthreads();

    int warp = tid >> 5, lane = tid & 31;
    int grp = lane >> 2, tid4 = lane & 3;

    float2 bv[8];
#pragma unroll
    for (int nb = 0; nb < 8; nb++) {
        int col = nb * 8 + tid4 * 2;
        bv[nb].x = bih[j * 64 + col]     + bhh[j * 64 + col];
        bv[nb].y = bih[j * 64 + col + 1] + bhh[j * 64 + col + 1];
    }

    float acc[8][4];
#pragma unroll
    for (int nb = 0; nb < 8; nb++)
#pragma unroll
        for (int x = 0; x < 4; x++) acc[nb][x] = 0.0f;

#pragma unroll
    for (int ks = 0; ks < 8; ks++) {
        int plane = ks * 4 + tid4;
        float4 af = *(const float4*)&AF[plane * 264 + warp * 32 + grp * 4];
        uint32_t a0h = f2tf32(af.x), a1h = f2tf32(af.y), a2h = f2tf32(af.z), a3h = f2tf32(af.w);
        uint32_t a0l = __float_as_uint(af.x - __uint_as_float(a0h));
        uint32_t a1l = __float_as_uint(af.y - __uint_as_float(a1h));
        uint32_t a2l = __float_as_uint(af.z - __uint_as_float(a2h));
        uint32_t a3l = __float_as_uint(af.w - __uint_as_float(a3h));
        const uint32_t* wrow = &WF[plane * 136];
#pragma unroll
        for (int nb = 0; nb < 8; nb++) {
            uint2 wb = *(const uint2*)&wrow[(nb * 8 + grp) * 2];
            mma_tf32(acc[nb], a0h, a1h, a2h, a3h, wb.x, wb.y);
            mma_tf32(acc[nb], a0l, a1l, a2l, a3l, wb.x, wb.y);
        }
    }

    float* O = g_xg + (size_t)j * BT_ * 64 + (size_t)bt0 * 64;
    int rbase = warp * 16;
    int row0 = rbase + grp, row1 = rbase + grp + 8;
#pragma unroll
    for (int nb = 0; nb < 8; nb++) {
        int col = nb * 8 + tid4 * 2;
        *(float2*)&O[row0 * 64 + col] = make_float2(acc[nb][0] + bv[nb].x, acc[nb][1] + bv[nb].y);
        *(float2*)&O[row1 * 64 + col] = make_float2(acc[nb][2] + bv[nb].x, acc[nb][3] + bv[nb].y);
    }
}

// ---------------- kernel 3: LSTM recurrence (monolithic, full parallelism) ------
__global__ void k3_lstm(const float* __restrict__ Whh)
{
    int gw   = blockIdx.x * 4 + (threadIdx.x >> 5);  // 0..4799
    int lane = threadIdx.x & 31;
    int j  = gw / 200;
    int bp = gw % 200;
    int seq = lane >> 4, jh = lane & 15;
    int b = bp * 2 + seq;

    float wr[4][16];
#pragma unroll
    for (int g = 0; g < 4; g++)
#pragma unroll
        for (int k = 0; k < 16; k++)
            wr[g][k] = Whh[j * 1024 + (g * 16 + jh) * 16 + k];

    const float* xgp  = g_xg  + ((size_t)j * B_ + b) * T_ * 64;
    float*       outp = g_qkv + ((size_t)j * B_ + b) * T_ * 16 + jh;

    float h = 0.0f, c = 0.0f;
    int srcbase = lane & 16;
    float n0 = xgp[jh], n1 = xgp[16 + jh], n2 = xgp[32 + jh], n3 = xgp[48 + jh];
    for (int t = 0; t < T_; ++t) {
        float a0 = n0, a1 = n1, a2 = n2, a3 = n3;
        if (t + 1 < T_) {
            const float* p = xgp + (t + 1) * 64;
            n0 = p[jh]; n1 = p[16 + jh]; n2 = p[32 + jh]; n3 = p[48 + jh];
        }
#pragma unroll
        for (int k = 0; k < 16; k++) {
            float hk = __shfl_sync(FULLMASK, h, srcbase + k);
            a0 = fmaf(wr[0][k], hk, a0);
            a1 = fmaf(wr[1][k], hk, a1);
            a2 = fmaf(wr[2][k], hk, a2);
            a3 = fmaf(wr[3][k], hk, a3);
        }
        c = sigf(a1) * c + sigf(a0) * tanhf_(a2);
        h = sigf(a3) * tanhf_(c);
        outp[t * 16] = h;
    }
}

// ---------------- kernel 4: triangular masked softmax attention, row-paired ------
// out[t] = (sum_{s<=t} e^{E_s} V_s + SufV[t]) / (sum_{s<=t} e^{E_s} + (199-t))
// Q prefetched to smem; merged fold-tree epilogue.
__global__ void __launch_bounds__(256, 2) k4_attn()
{
    __shared__ float Qs[200 * 16];
    __shared__ float Ks[224 * 20];     // rows 200..223 zero-filled
    __shared__ float Vs[224 * 20];
    __shared__ float Suf[200 * 16];
    __shared__ float Seg[8][16];

    int b  = blockIdx.x % 400;
    int br = blockIdx.x / 400;
    int tid = threadIdx.x;
    const float* qp = g_qkv + ((size_t)(br * 3 + 0) * B_ + b) * T_ * 16;
    const float* kp = g_qkv + ((size_t)(br * 3 + 1) * B_ + b) * T_ * 16;
    const float* vp = g_qkv + ((size_t)(br * 3 + 2) * B_ + b) * T_ * 16;

    for (int idx = tid; idx < 3200; idx += 256) {
        int t = idx >> 4, f = idx & 15;
        Qs[idx]        = qp[idx];
        Ks[t * 20 + f] = kp[idx];
        Vs[t * 20 + f] = vp[idx];
    }
    for (int idx = 3200 + tid; idx < 3584; idx += 256) {
        int t = idx >> 4, f = idx & 15;
        Ks[t * 20 + f] = 0.0f;
        Vs[t * 20 + f] = 0.0f;
    }
    __syncthreads();

    if (tid < 128) {
        int f = tid & 15, seg = tid >> 4;
        float s = 0.0f;
        for (int tt = 0; tt < 25; tt++) s += Vs[(seg * 25 + tt) * 20 + f];
        Seg[seg][f] = s;
    }
    __syncthreads();
    if (tid < 128) {
        int f = tid & 15, seg = tid >> 4;
        float run = 0.0f;
        for (int s2 = seg + 1; s2 < 8; s2++) run += Seg[s2][f];
        for (int tt = 24; tt >= 0; tt--) {
            int t = seg * 25 + tt;
            Suf[t * 16 + f] = run;
            run += Vs[t * 20 + f];
        }
    }
    __syncthreads();

    int warp = tid >> 5, lane = tid & 31;
    bool hi16 = (lane & 16) != 0;
    float* attp = g_att + ((size_t)br * B_ + b) * T_ * 16;

    for (int tp = warp; tp < 100; tp += 8) {
        int t0 = tp * 2, t1 = t0 + 1;
        const float4* q0r = (const float4*)&Qs[t0 * 16];
        const float4* q1r = (const float4*)&Qs[t1 * 16];
        float4 qa0 = q0r[0], qa1 = q0r[1], qa2 = q0r[2], qa3 = q0r[3];
        float4 qb0 = q1r[0], qb1 = q1r[1], qb2 = q1r[2], qb3 = q1r[3];

        float acc0[16], acc1[16];
#pragma unroll
        for (int f2 = 0; f2 < 16; f2++) { acc0[f2] = 0.0f; acc1[f2] = 0.0f; }
        float z0 = 0.0f, z1 = 0.0f;

        int nch = (t1 >> 5) + 1;
#pragma unroll
        for (int i = 0; i < 7; i++) {
            if (i < nch) {                        // warp-uniform
                int s = lane + (i << 5);
                const float4* kr = (const float4*)&Ks[s * 20];
                float4 k0 = kr[0], k1 = kr[1], k2 = kr[2], k3 = kr[3];
                float e0 = qa0.x*k0.x + qa0.y*k0.y + qa0.z*k0.z + qa0.w*k0.w
                         + qa1.x*k1.x + qa1.y*k1.y + qa1.z*k1.z + qa1.w*k1.w
                         + qa2.x*k2.x + qa2.y*k2.y + qa2.z*k2.z + qa2.w*k2.w
                         + qa3.x*k3.x + qa3.y*k3.y + qa3.z*k3.z + qa3.w*k3.w;
                float e1 = qb0.x*k0.x + qb0.y*k0.y + qb0.z*k0.z + qb0.w*k0.w
                         + qb1.x*k1.x + qb1.y*k1.y + qb1.z*k1.z + qb1.w*k1.w
                         + qb2.x*k2.x + qb2.y*k2.y + qb2.z*k2.z + qb2.w*k2.w
                         + qb3.x*k3.x + qb3.y*k3.y + qb3.z*k3.z + qb3.w*k3.w;
                float p0 = (s <= t0) ? __expf(e0 * 0.25f) : 0.0f;
                float p1 = (s <= t1) ? __expf(e1 * 0.25f) : 0.0f;
                z0 += p0; z1 += p1;
                const float4* vr = (const float4*)&Vs[s * 20];
                float4 v0 = vr[0], v1 = vr[1], v2 = vr[2], v3 = vr[3];
                acc0[0]  = fmaf(p0, v0.x, acc0[0]);  acc1[0]  = fmaf(p1, v0.x, acc1[0]);
                acc0[1]  = fmaf(p0, v0.y, acc0[1]);  acc1[1]  = fmaf(p1, v0.y, acc1[1]);
                acc0[2]  = fmaf(p0, v0.z, acc0[2]);  acc1[2]  = fmaf(p1, v0.z, acc1[2]);
                acc0[3]  = fmaf(p0, v0.w, acc0[3]);  acc1[3]  = fmaf(p1, v0.w, acc1[3]);
                acc0[4]  = fmaf(p0, v1.x, acc0[4]);  acc1[4]  = fmaf(p1, v1.x, acc1[4]);
                acc0[5]  = fmaf(p0, v1.y, acc0[5]);  acc1[5]  = fmaf(p1, v1.y, acc1[5]);
                acc0[6]  = fmaf(p0, v1.z, acc0[6]);  acc1[6]  = fmaf(p1, v1.z, acc1[6]);
                acc0[7]  = fmaf(p0, v1.w, acc0[7]);  acc1[7]  = fmaf(p1, v1.w, acc1[7]);
                acc0[8]  = fmaf(p0, v2.x, acc0[8]);  acc1[8]  = fmaf(p1, v2.x, acc1[8]);
                acc0[9]  = fmaf(p0, v2.y, acc0[9]);  acc1[9]  = fmaf(p1, v2.y, acc1[9]);
                acc0[10] = fmaf(p0, v2.z, acc0[10]); acc1[10] = fmaf(p1, v2.z, acc1[10]);
                acc0[11] = fmaf(p0, v2.w, acc0[11]); acc1[11] = fmaf(p1, v2.w, acc1[11]);
                acc0[12] = fmaf(p0, v3.x, acc0[12]); acc1[12] = fmaf(p1, v3.x, acc1[12]);
                acc0[13] = fmaf(p0, v3.y, acc0[13]); acc1[13] = fmaf(p1, v3.y, acc1[13]);
                acc0[14] = fmaf(p0, v3.z, acc0[14]); acc1[14] = fmaf(p1, v3.z, acc1[14]);
                acc0[15] = fmaf(p0, v3.w, acc0[15]); acc1[15] = fmaf(p1, v3.w, acc1[15]);
            }
        }

        float zz;
        {
            float zm = hi16 ? z1 : z0;
            float zo = hi16 ? z0 : z1;
            zz = zm + __shfl_xor_sync(FULLMASK, zo, 16);
#pragma unroll
            for (int off = 8; off; off >>= 1) zz += __shfl_xor_sync(FULLMASK, zz, off);
        }

        float m16[16];
#pragma unroll
        for (int f2 = 0; f2 < 16; f2++) {
            float mine = hi16 ? acc1[f2] : acc0[f2];
            float send = hi16 ? acc0[f2] : acc1[f2];
            m16[f2] = mine + __shfl_xor_sync(FULLMASK, send, 16);
        }
        float r8[8];
        {
            bool hi = (lane & 8) != 0;
#pragma unroll
            for (int f2 = 0; f2 < 8; f2++) {
                float keep = hi ? m16[f2 + 8] : m16[f2];
                float send = hi ? m16[f2]     : m16[f2 + 8];
                r8[f2] = keep + __shfl_xor_sync(FULLMASK, send, 8);
            }
        }
        float r4[4];
        {
            bool hi = (lane & 4) != 0;
#pragma unroll
            for (int f2 = 0; f2 < 4; f2++) {
                float keep = hi ? r8[f2 + 4] : r8[f2];
                float send = hi ? r8[f2]     : r8[f2 + 4];
                r4[f2] = keep + __shfl_xor_sync(FULLMASK, send, 4);
            }
        }
        float r2[2];
        {
            bool hi = (lane & 2) != 0;
#pragma unroll
            for (int f2 = 0; f2 < 2; f2++) {
                float keep = hi ? r4[f2 + 2] : r4[f2];
                float send = hi ? r4[f2]     : r4[f2 + 2];
                r2[f2] = keep + __shfl_xor_sync(FULLMASK, send, 2);
            }
        }
        float r1;
        {
            bool hi = (lane & 1) != 0;
            float keep = hi ? r2[1] : r2[0];
            float send = hi ? r2[0] : r2[1];
            r1 = keep + __shfl_xor_sync(FULLMASK, send, 1);
        }

        int f = lane & 15;
        int t = hi16 ? t1 : t0;
        float Z = zz + (float)(199 - t);
        attp[t * 16 + f] = (r1 + Suf[t * 16 + f]) / Z;
    }
}

// ---------------- kernel 5: combine + LN2 + complex linear + LN3 + PReLU + res --
__global__ void k5_final(const float* __restrict__ inp,
                         const float* __restrict__ ln2w, const float* __restrict__ ln2b,
                         const float* __restrict__ lrw,  const float* __restrict__ lrb,
                         const float* __restrict__ liw,  const float* __restrict__ lib,
                         const float* __restrict__ ln3w, const float* __restrict__ ln3b,
                         const float* __restrict__ pa,   float* __restrict__ out)
{
    __shared__ __align__(16) float zs[64][84];
    int bid = blockIdx.x;
    int tile = bid % 5, nf = bid / 5;
    int n = nf / 100, f = nf % 100;
    int t0 = tile * 40;
    int tid = threadIdx.x;
    int lane = tid & 31, warp = tid >> 5;
    int c0 = lane, c1 = lane + 32;

    float Wr0[16], Wi0[16], Wr1[16], Wi1[16];
#pragma unroll
    for (int k = 0; k < 16; k++) {
        Wr0[k] = lrw[c0 * 16 + k]; Wi0[k] = liw[c0 * 16 + k];
        Wr1[k] = lrw[c1 * 16 + k]; Wi1[k] = liw[c1 * 16 + k];
    }
    float br0 = lrb[c0], br1 = lrb[c1], bi0 = lib[c0], bi1 = lib[c1];
    float w3_0 = ln3w[c0], w3_1 = ln3w[c1], b3_0 = ln3b[c0], b3_1 = ln3b[c1];
    int fh = lane & 15;
    float w2 = ln2w[fh], b2 = ln2b[fh];
    float a = pa[0];
    const size_t bs = (size_t)B_ * T_ * 16;
    int b = nf;

#pragma unroll
    for (int kk = 0; kk < 5; kk++) {
        int tt = warp + kk * 8;
        int t = t0 + tt;

        int brb = (lane < 16) ? 0 : 4;
        const float* ap = g_att + (size_t)brb * bs + ((size_t)b * T_ + t) * 16 + fh;
        float a0 = ap[0], a1 = ap[bs], a2 = ap[2 * bs], a3 = ap[3 * bs];
        float val = (lane < 16) ? (a0 - a1 - a2 - a3) : (a0 + a1 + a2 - a3);

        float s = val, ss = val * val;
#pragma unroll
        for (int off = 8; off; off >>= 1) {
            s  += __shfl_xor_sync(FULLMASK, s,  off);
            ss += __shfl_xor_sync(FULLMASK, ss, off);
        }
        float mean = s * (1.0f / 16.0f);
        float rs = rsqrtf(ss * (1.0f / 16.0f) - mean * mean + 1e-5f);
        float y = (val - mean) * rs * w2 + b2;

        float or0 = br0 - bi0, or1 = br1 - bi1, oi0 = br0 + bi0, oi1 = br1 + bi1;
#pragma unroll
        for (int k = 0; k < 16; k++) {
            float xr = __shfl_sync(FULLMASK, y, k);
            float xi = __shfl_sync(FULLMASK, y, 16 + k);
            or0 = fmaf(Wr0[k], xr, or0); or0 = fmaf(-Wi0[k], xi, or0);
            oi0 = fmaf(Wr0[k], xi, oi0); oi0 = fmaf( Wi0[k], xr, oi0);
            or1 = fmaf(Wr1[k], xr, or1); or1 = fmaf(-Wi1[k], xi, or1);
            oi1 = fmaf(Wr1[k], xi, oi1); oi1 = fmaf( Wi1[k], xr, oi1);
        }

        float sr = or0 + or1, sqr = or0 * or0 + or1 * or1;
        float si = oi0 + oi1, sqi = oi0 * oi0 + oi1 * oi1;
#pragma unroll
        for (int off = 16; off; off >>= 1) {
            sr  += __shfl_xor_sync(FULLMASK, sr,  off);
            sqr += __shfl_xor_sync(FULLMASK, sqr, off);
            si  += __shfl_xor_sync(FULLMASK, si,  off);
            sqi += __shfl_xor_sync(FULLMASK, sqi, off);
        }
        float mr = sr * (1.0f / 64.0f), mi = si * (1.0f / 64.0f);
        float rr  = rsqrtf(sqr * (1.0f / 64.0f) - mr * mr + 1e-5f);
        float rim = rsqrtf(sqi * (1.0f / 64.0f) - mi * mi + 1e-5f);
        float zr0 = (or0 - mr) * rr  * w3_0 + b3_0;
        float zr1 = (or1 - mr) * rr  * w3_1 + b3_1;
        float zi0 = (oi0 - mi) * rim * w3_0 + b3_0;
        float zi1 = (oi1 - mi) * rim * w3_1 + b3_1;
        zr0 = zr0 >= 0.0f ? zr0 : a * zr0;
        zr1 = zr1 >= 0.0f ? zr1 : a * zr1;
        zi0 = zi0 >= 0.0f ? zi0 : a * zi0;
        zi1 = zi1 >= 0.0f ? zi1 : a * zi1;

        zs[c0][tt * 2 + 0] = zr0;
        zs[c0][tt * 2 + 1] = zi0;
        zs[c1][tt * 2 + 0] = zr1;
        zs[c1][tt * 2 + 1] = zi1;
    }
    __syncthreads();

#pragma unroll
    for (int it = 0; it < 5; it++) {
        int idx = it * 256 + tid;
        int c = idx / 20, part = idx % 20;
        size_t g = ((size_t)(n * 64 + c) * 100 + f) * 400 + (size_t)t0 * 2 + part * 4;
        float4 z = *(float4*)&zs[c][part * 4];
        float4 iv = *(const float4*)(inp + g);
        z.x += iv.x; z.y += iv.y; z.z += iv.z; z.w += iv.w;
        *(float4*)(out + g) = z;
    }
}

// ---------------- launch ---------------------------------------------------------
extern "C" void kernel_launch(void* const* d_in, const int* in_sizes, int n_in,
                              void* d_out, int out_size)
{
    const float* inp    = (const float*)d_in[0];
    const float* Wih    = (const float*)d_in[1];
    const float* Whh    = (const float*)d_in[2];
    const float* bih    = (const float*)d_in[3];
    const float* bhh    = (const float*)d_in[4];
    const float* ln1w   = (const float*)d_in[5];
    const float* ln1b   = (const float*)d_in[6];
    const float* ln2w   = (const float*)d_in[7];
    const float* ln2b   = (const float*)d_in[8];
    const float* lrw    = (const float*)d_in[9];
    const float* lrb    = (const float*)d_in[10];
    const float* liw    = (const float*)d_in[11];
    const float* lib    = (const float*)d_in[12];
    const float* ln3w   = (const float*)d_in[13];
    const float* ln3b   = (const float*)d_in[14];
    const float* prelua = (const float*)d_in[15];
    float* out = (float*)d_out;

    k1_ln1<<<2000, 256>>>(inp, ln1w, ln1b);
    dim3 g2(625, 24);
    k2_gemm<<<g2, 256>>>(Wih, bih, bhh);
    k3_lstm<<<1200, 128>>>(Whh);
    k4_attn<<<3200, 256>>>();
    k5_final<<<2000, 256>>>(inp, ln2w, ln2b, lrw, lrb, liw, lib, ln3w, ln3b, prelua, out);
}